// round 14
// baseline (speedup 1.0000x reference)
#include <cuda_runtime.h>
#include <cuda_fp16.h>
#include <cstdint>
#include <mma.h>

using namespace nvcuda;
typedef unsigned long long ull;

#define Bn 4
#define Hh 128
#define Wwidth 128
#define HW (128*128)

// ---------------- packed fp32x2 helpers ------------------------------------
__device__ __forceinline__ ull pk(float lo, float hi) {
    ull r; asm("mov.b64 %0, {%1,%2};" : "=l"(r) : "f"(lo), "f"(hi)); return r;
}
__device__ __forceinline__ void upk(ull v, float& lo, float& hi) {
    asm("mov.b64 {%0,%1}, %2;" : "=f"(lo), "=f"(hi) : "l"(v));
}
__device__ __forceinline__ ull ffma2(ull a, ull b, ull c) {
    ull d; asm("fma.rn.f32x2 %0, %1, %2, %3;" : "=l"(d) : "l"(a), "l"(b), "l"(c)); return d;
}

// -------- scratch --------
__device__ float  g_om [Bn*216*HW];            // conv_om raw (fp32 NCHW)
__device__ float  g_em [Bn*72*HW];             // sigmoid(conv em2) fp32 NCHW
// conv-input channel-interleaved fp16 planes: [b][chunk16][h][w][ci16]
__device__ __half g_ofi[(size_t)Bn*64*HW];     // offset_feat
__device__ __half g_si [(size_t)Bn*64*HW];     // share (em1 input)
__device__ __half g_e1i[(size_t)Bn*64*HW];     // em1 output (em2 input)
// combined sampling plane: [b][g8][h][w][x8|share8] fp16 (32 B per pixel)
__device__ __half g_comb[(size_t)Bn*8*HW*16];
// packed fp16 weights [CoP][Ktot], K index = (chunk*9+tap)*16+ci
__device__ __half g_wom[256*576];
__device__ __half g_we1[64*1152];
__device__ __half g_we2[128*576];

// ---------------------------------------------------------------------------
// fused weight pack
// ---------------------------------------------------------------------------
__global__ void pack_all_kernel(const float* __restrict__ w0,
                                const float* __restrict__ w1,
                                const float* __restrict__ w2,
                                __half* __restrict__ d0,
                                __half* __restrict__ d1,
                                __half* __restrict__ d2)
{
    const int t = blockIdx.y;
    const float* w; __half* d; int Co, CoP, CIN;
    if (t == 0)      { w = w0; d = d0; Co = 216; CoP = 256; CIN = 64; }
    else if (t == 1) { w = w1; d = d1; Co = 64;  CoP = 64;  CIN = 128; }
    else             { w = w2; d = d2; Co = 72;  CoP = 128; CIN = 64; }

    int idx = blockIdx.x * 256 + threadIdx.x;
    int Ktot = CIN * 9;
    if (idx >= CoP * Ktot) return;
    int co = idx / Ktot, k = idx % Ktot;
    int chunk = k / 144, rem = k % 144, tap = rem / 16, ci = rem % 16;
    int cin = chunk * 16 + ci;
    float v = (co < Co) ? w[((size_t)co * CIN + cin) * 9 + tap] : 0.f;
    d[idx] = __float2half_rn(v);
}

// ---------------------------------------------------------------------------
// fused input transpose. t=0: offF -> ofi. t=1: share -> si AND comb[..][8:16].
// t=2: x -> comb[..][0:8].
// ---------------------------------------------------------------------------
__global__ void __launch_bounds__(128) split_all_kernel(
    const float* __restrict__ in0, const float* __restrict__ in1,
    const float* __restrict__ in2,
    __half* __restrict__ ofi, __half* __restrict__ si, __half* __restrict__ comb)
{
    const int px = threadIdx.x;
    const int h = blockIdx.x;
    const int z = blockIdx.z;
    const int t = z >> 4;
    const int b = (z >> 2) & 3, chunk = z & 3;
    const float* in = (t == 0) ? in0 : (t == 1) ? in1 : in2;

    const float* src = in + (size_t)(b * 64 + chunk * 16) * HW + h * Wwidth + px;
    __half hv[16];
    #pragma unroll
    for (int ci = 0; ci < 16; ci++) hv[ci] = __float2half_rn(src[(size_t)ci * HW]);

    const size_t pix = (size_t)h * Wwidth + px;
    if (t == 0 || t == 1) {
        __half* o = (t == 0) ? ofi : si;
        size_t off = (((size_t)(b * 4 + chunk) * Hh + h) * Wwidth + px) * 16;
        ((uint4*)(o + off))[0] = ((const uint4*)hv)[0];
        ((uint4*)(o + off))[1] = ((const uint4*)hv)[1];
    }
    if (t == 1 || t == 2) {
        // comb record: [b][g][pix][16]; x at +0, share at +8
        int lane = (t == 2) ? 0 : 8;
        size_t o0 = (((size_t)(b * 8 + chunk * 2)     * HW) + pix) * 16 + lane;
        size_t o1 = (((size_t)(b * 8 + chunk * 2 + 1) * HW) + pix) * 16 + lane;
        *(uint4*)(comb + o0) = ((const uint4*)hv)[0];
        *(uint4*)(comb + o1) = ((const uint4*)hv)[1];
    }
}

// ---------------------------------------------------------------------------
// conv body constants (R9 proven: 512 thr, 2 rows, warp tile 32co x 32px)
// ---------------------------------------------------------------------------
#define XSZ2 (4*132*16)
#define SMEM_CONV (XSZ2*2 + 64*144*2)   // 35328 B

// Merged om + em1 kernel. blockIdx.z == 0 -> em1 (long blocks first);
// z in 1..4 -> om co-tile z-1.
__global__ void __launch_bounds__(512) conv_om_em1_kernel(
    const __half* __restrict__ ofi, const __half* __restrict__ si,
    const __half* __restrict__ wom, const __half* __restrict__ we1,
    const float* __restrict__ b_om, const float* __restrict__ b_em1,
    float* __restrict__ omOut, __half* __restrict__ e1Out)
{
    extern __shared__ __align__(16) char smem_raw[];
    __half* s_x = (__half*)smem_raw;
    __half* s_w = (__half*)(smem_raw + XSZ2 * 2);
    float*  sEp = (float*)smem_raw;

    const int tid = threadIdx.x;
    const int h2 = blockIdx.x, b = blockIdx.y;
    const bool isEm1 = (blockIdx.z == 0);
    const int coTile = isEm1 ? 0 : (blockIdx.z - 1);
    const int chunks = isEm1 ? 8 : 4;
    const int Ktot   = chunks * 144;
    const __half* x0 = isEm1 ? si : ofi;
    const __half* wA = isEm1 ? we1 : wom;
    const int h0 = h2 * 2;
    const int warp = tid >> 5;
    const int rowSub = warp >> 3;
    const int coSub  = (warp >> 2) & 1;
    const int nSub   = warp & 3;

    wmma::fragment<wmma::accumulator, 16, 16, 16, float> acc[2][2];
    #pragma unroll
    for (int cf = 0; cf < 2; cf++)
        #pragma unroll
        for (int nf = 0; nf < 2; nf++) wmma::fill_fragment(acc[cf][nf], 0.f);

    if (tid < 32) {
        int r = tid >> 3, q = tid & 7;
        const int cols[4] = {0, 129, 130, 131};
        int scol = cols[q >> 1];
        uint4 z = {0, 0, 0, 0};
        ((uint4*)(s_x + (r * 132 + scol) * 16))[q & 1] = z;
    }

    for (int chunk = 0; chunk < chunks; chunk++) {
        const __half* base = (chunk < 4)
            ? x0 + ((size_t)b * 4 + chunk) * HW * 16
            : ofi + ((size_t)b * 4 + (chunk - 4)) * HW * 16;
        for (int u = tid; u < 1024; u += 512) {
            int r = u >> 8, c = u & 255;
            int row = h0 - 1 + r;
            uint4 v = {0, 0, 0, 0};
            if (row >= 0 && row < Hh)
                v = *(const uint4*)(base + (size_t)row * 2048 + c * 8);
            *(uint4*)(s_x + (r * 132 + 1) * 16 + c * 8) = v;
        }
        for (int u = tid; u < 1152; u += 512) {
            int co = u / 18, c = u - co * 18;
            *(uint4*)(s_w + co * 144 + c * 8) =
                *(const uint4*)(wA + (size_t)(coTile * 64 + co) * Ktot + chunk * 144 + c * 8);
        }
        __syncthreads();

        #pragma unroll
        for (int tap = 0; tap < 9; tap++) {
            const int dr = tap / 3, dc = tap % 3;
            wmma::fragment<wmma::matrix_a, 16, 16, 16, __half, wmma::row_major> af[2];
            #pragma unroll
            for (int cf = 0; cf < 2; cf++)
                wmma::load_matrix_sync(af[cf], s_w + (coSub * 32 + cf * 16) * 144 + tap * 16, 144);
            wmma::fragment<wmma::matrix_b, 16, 16, 16, __half, wmma::col_major> bfr[2];
            #pragma unroll
            for (int nf = 0; nf < 2; nf++) {
                int scol = nSub * 32 + nf * 16 + dc;
                wmma::load_matrix_sync(bfr[nf], s_x + ((rowSub + dr) * 132 + scol) * 16, 16);
            }
            #pragma unroll
            for (int cf = 0; cf < 2; cf++)
                #pragma unroll
                for (int nf = 0; nf < 2; nf++)
                    wmma::mma_sync(acc[cf][nf], af[cf], bfr[nf], acc[cf][nf]);
        }
        __syncthreads();
    }

    #pragma unroll
    for (int r = 0; r < 2; r++) {
        if (rowSub == r) {
            #pragma unroll
            for (int cf = 0; cf < 2; cf++)
                #pragma unroll
                for (int nf = 0; nf < 2; nf++)
                    wmma::store_matrix_sync(
                        sEp + (coSub * 32 + cf * 16) * 136 + (nSub * 32 + nf * 16),
                        acc[cf][nf], 136, wmma::mem_row_major);
        }
        __syncthreads();

        const int h = h0 + r;
        const int px = tid & 127;
        if (isEm1) {
            int ch = tid >> 7;
            __half hv[16];
            #pragma unroll
            for (int ci = 0; ci < 16; ci++) {
                int co = ch * 16 + ci;
                float v = sEp[co * 136 + px] + b_em1[co];
                v = (v >= 0.f) ? v : 0.1f * v;
                hv[ci] = __float2half_rn(v);
            }
            size_t o = (((size_t)(b * 4 + ch) * Hh + h) * Wwidth + px) * 16;
            ((uint4*)(e1Out + o))[0] = ((const uint4*)hv)[0];
            ((uint4*)(e1Out + o))[1] = ((const uint4*)hv)[1];
        } else {
            for (int co = tid >> 7; co < 64; co += 4) {
                int oc = coTile * 64 + co;
                if (oc < 216)
                    omOut[((size_t)b * 216 + oc) * HW + h * Wwidth + px] =
                        sEp[co * 136 + px] + b_om[oc];
            }
        }
        __syncthreads();
    }
}

// em2 conv (same R9 body, sigmoid epilogue)
__global__ void __launch_bounds__(512) conv_em2_kernel(
    const __half* __restrict__ e1i, const __half* __restrict__ we2,
    const float* __restrict__ b_em2, float* __restrict__ emOut)
{
    extern __shared__ __align__(16) char smem_raw[];
    __half* s_x = (__half*)smem_raw;
    __half* s_w = (__half*)(smem_raw + XSZ2 * 2);
    float*  sEp = (float*)smem_raw;

    const int tid = threadIdx.x;
    const int h2 = blockIdx.x, b = blockIdx.y, coTile = blockIdx.z;
    const int h0 = h2 * 2;
    const int warp = tid >> 5;
    const int rowSub = warp >> 3;
    const int coSub  = (warp >> 2) & 1;
    const int nSub   = warp & 3;

    wmma::fragment<wmma::accumulator, 16, 16, 16, float> acc[2][2];
    #pragma unroll
    for (int cf = 0; cf < 2; cf++)
        #pragma unroll
        for (int nf = 0; nf < 2; nf++) wmma::fill_fragment(acc[cf][nf], 0.f);

    if (tid < 32) {
        int r = tid >> 3, q = tid & 7;
        const int cols[4] = {0, 129, 130, 131};
        int scol = cols[q >> 1];
        uint4 z = {0, 0, 0, 0};
        ((uint4*)(s_x + (r * 132 + scol) * 16))[q & 1] = z;
    }

    for (int chunk = 0; chunk < 4; chunk++) {
        const __half* base = e1i + ((size_t)b * 4 + chunk) * HW * 16;
        for (int u = tid; u < 1024; u += 512) {
            int r = u >> 8, c = u & 255;
            int row = h0 - 1 + r;
            uint4 v = {0, 0, 0, 0};
            if (row >= 0 && row < Hh)
                v = *(const uint4*)(base + (size_t)row * 2048 + c * 8);
            *(uint4*)(s_x + (r * 132 + 1) * 16 + c * 8) = v;
        }
        for (int u = tid; u < 1152; u += 512) {
            int co = u / 18, c = u - co * 18;
            *(uint4*)(s_w + co * 144 + c * 8) =
                *(const uint4*)(we2 + (size_t)(coTile * 64 + co) * 576 + chunk * 144 + c * 8);
        }
        __syncthreads();

        #pragma unroll
        for (int tap = 0; tap < 9; tap++) {
            const int dr = tap / 3, dc = tap % 3;
            wmma::fragment<wmma::matrix_a, 16, 16, 16, __half, wmma::row_major> af[2];
            #pragma unroll
            for (int cf = 0; cf < 2; cf++)
                wmma::load_matrix_sync(af[cf], s_w + (coSub * 32 + cf * 16) * 144 + tap * 16, 144);
            wmma::fragment<wmma::matrix_b, 16, 16, 16, __half, wmma::col_major> bfr[2];
            #pragma unroll
            for (int nf = 0; nf < 2; nf++) {
                int scol = nSub * 32 + nf * 16 + dc;
                wmma::load_matrix_sync(bfr[nf], s_x + ((rowSub + dr) * 132 + scol) * 16, 16);
            }
            #pragma unroll
            for (int cf = 0; cf < 2; cf++)
                #pragma unroll
                for (int nf = 0; nf < 2; nf++)
                    wmma::mma_sync(acc[cf][nf], af[cf], bfr[nf], acc[cf][nf]);
        }
        __syncthreads();
    }

    #pragma unroll
    for (int r = 0; r < 2; r++) {
        if (rowSub == r) {
            #pragma unroll
            for (int cf = 0; cf < 2; cf++)
                #pragma unroll
                for (int nf = 0; nf < 2; nf++)
                    wmma::store_matrix_sync(
                        sEp + (coSub * 32 + cf * 16) * 136 + (nSub * 32 + nf * 16),
                        acc[cf][nf], 136, wmma::mem_row_major);
        }
        __syncthreads();

        const int h = h0 + r;
        const int px = tid & 127;
        for (int co = tid >> 7; co < 64; co += 4) {
            int oc = coTile * 64 + co;
            if (oc < 72) {
                float v = sEp[co * 136 + px] + b_em2[oc];
                emOut[((size_t)b * 72 + oc) * HW + h * Wwidth + px] =
                    1.f / (1.f + __expf(-v));
            }
        }
        __syncthreads();
    }
}

// ---------------------------------------------------------------------------
// Both deformable convs; x and share sample the SAME combined plane so corner
// cache lines are shared between the two halves.
// ---------------------------------------------------------------------------
__global__ void __launch_bounds__(256) deform_kernel(
    const float* __restrict__ w_dc, const float* __restrict__ b_dc,
    const __half* __restrict__ comb, float* __restrict__ out)
{
    __shared__ __align__(16) float s_w[8][9][8];
    __shared__ float s_b[8];

    const int tid  = threadIdx.x;
    const int half = tid >> 7;
    const int w    = tid & 127;
    const int h    = blockIdx.x;
    const int bg   = blockIdx.y;
    const int b    = bg >> 3, g = bg & 7;

    for (int e = tid; e < 576; e += 256) {
        int c = e / 72, r = e % 72;
        int kk = r / 8, co = r % 8;
        s_w[c][kk][co] = w_dc[((size_t)(g * 8 + co) * 8 + c) * 9 + kk];
    }
    if (tid < 8) s_b[tid] = b_dc[g * 8 + tid];
    __syncthreads();

    const int pix = h * Wwidth + w;
    const float* omB = g_om + (size_t)b * 216 * HW + pix;
    const float* emB = g_em + (size_t)b * 72 * HW + pix;
    const __half* src = comb + ((size_t)(b * 8 + g) * HW) * 16 + half * 8;

    ull acc[4];
    #pragma unroll
    for (int j = 0; j < 4; j++) acc[j] = 0ull;

    #pragma unroll
    for (int kk = 0; kk < 9; kk++) {
        const int kh = kk / 3, kw = kk % 3;
        float dy = omB[(size_t)(g * 18 + 2 * kk) * HW];
        float dx = omB[(size_t)(g * 18 + 2 * kk + 1) * HW];
        float mask;
        if (half == 0) {
            float mz = omB[(size_t)(144 + g * 9 + kk) * HW];
            mask = 1.f / (1.f + __expf(-mz));
        } else {
            mask = emB[(size_t)(g * 9 + kk) * HW];
        }

        float py = (float)(h - 1 + kh) + dy;
        float px = (float)(w - 1 + kw) + dx;
        float fy = floorf(py), fx = floorf(px);
        float ly = py - fy, lx = px - fx;
        int y0 = (int)fy, x0 = (int)fx;
        int y1 = y0 + 1, x1 = x0 + 1;

        float w00 = (1.f - ly) * (1.f - lx);
        float w01 = (1.f - ly) * lx;
        float w10 = ly * (1.f - lx);
        float w11 = ly * lx;
        if (y0 < 0 || y0 >= Hh)     { w00 = 0.f; w01 = 0.f; }
        if (y1 < 0 || y1 >= Hh)     { w10 = 0.f; w11 = 0.f; }
        if (x0 < 0 || x0 >= Wwidth) { w00 = 0.f; w10 = 0.f; }
        if (x1 < 0 || x1 >= Wwidth) { w01 = 0.f; w11 = 0.f; }

        int cy0 = min(max(y0, 0), Hh - 1),     cy1 = min(max(y1, 0), Hh - 1);
        int cx0 = min(max(x0, 0), Wwidth - 1), cx1 = min(max(x1, 0), Wwidth - 1);
        int i00 = (cy0 * Wwidth + cx0) * 16, i01 = (cy0 * Wwidth + cx1) * 16;
        int i10 = (cy1 * Wwidth + cx0) * 16, i11 = (cy1 * Wwidth + cx1) * 16;

        float4 r00 = *(const float4*)(src + i00);
        float4 r01 = *(const float4*)(src + i01);
        float4 r10 = *(const float4*)(src + i10);
        float4 r11 = *(const float4*)(src + i11);
        const __half2* h00 = (const __half2*)&r00;
        const __half2* h01 = (const __half2*)&r01;
        const __half2* h10 = (const __half2*)&r10;
        const __half2* h11 = (const __half2*)&r11;

        float vv[8];
        #pragma unroll
        for (int j2 = 0; j2 < 4; j2++) {
            float2 f00 = __half22float2(h00[j2]);
            float2 f01 = __half22float2(h01[j2]);
            float2 f10 = __half22float2(h10[j2]);
            float2 f11 = __half22float2(h11[j2]);
            vv[2 * j2]     = (w00 * f00.x + w01 * f01.x + w10 * f10.x + w11 * f11.x) * mask;
            vv[2 * j2 + 1] = (w00 * f00.y + w01 * f01.y + w10 * f10.y + w11 * f11.y) * mask;
        }

        #pragma unroll
        for (int c = 0; c < 8; c++) {
            ull xs = pk(vv[c], vv[c]);
            #pragma unroll
            for (int j = 0; j < 4; j++) {
                ull wp = *(const ull*)&s_w[c][kk][2 * j];
                acc[j] = ffma2(xs, wp, acc[j]);
            }
        }
    }

    float* ob = out + (size_t)half * Bn * 64 * HW + (size_t)(b * 64 + g * 8) * HW + pix;
    #pragma unroll
    for (int j = 0; j < 4; j++) {
        float v0, v1;
        upk(acc[j], v0, v1);
        ob[(size_t)(2 * j) * HW]     = v0 + s_b[2 * j];
        ob[(size_t)(2 * j + 1) * HW] = v1 + s_b[2 * j + 1];
    }
}

// ---------------------------------------------------------------------------
extern "C" void kernel_launch(void* const* d_in, const int* in_sizes, int n_in,
                              void* d_out, int out_size)
{
    const float* x      = (const float*)d_in[0];
    const float* share  = (const float*)d_in[1];
    const float* offF   = (const float*)d_in[2];
    const float* w_om   = (const float*)d_in[3];
    const float* b_om   = (const float*)d_in[4];
    const float* w_em1  = (const float*)d_in[5];
    const float* b_em1  = (const float*)d_in[6];
    const float* w_em2  = (const float*)d_in[7];
    const float* b_em2  = (const float*)d_in[8];
    const float* w_dc   = (const float*)d_in[9];
    const float* b_dc   = (const float*)d_in[10];
    float* out = (float*)d_out;

    float *pom, *pem;
    __half *psi, *pofi, *pe1i, *pcomb, *pwom, *pwe1, *pwe2;
    cudaGetSymbolAddress((void**)&pom,   g_om);
    cudaGetSymbolAddress((void**)&pem,   g_em);
    cudaGetSymbolAddress((void**)&psi,   g_si);
    cudaGetSymbolAddress((void**)&pofi,  g_ofi);
    cudaGetSymbolAddress((void**)&pe1i,  g_e1i);
    cudaGetSymbolAddress((void**)&pcomb, g_comb);
    cudaGetSymbolAddress((void**)&pwom,  g_wom);
    cudaGetSymbolAddress((void**)&pwe1,  g_we1);
    cudaGetSymbolAddress((void**)&pwe2,  g_we2);

    cudaFuncSetAttribute(conv_om_em1_kernel,
                         cudaFuncAttributeMaxDynamicSharedMemorySize, SMEM_CONV);
    cudaFuncSetAttribute(conv_em2_kernel,
                         cudaFuncAttributeMaxDynamicSharedMemorySize, SMEM_CONV);

    pack_all_kernel<<<dim3(576, 3), 256>>>(w_om, w_em1, w_em2,                    // 1
                                           pwom, pwe1, pwe2);
    split_all_kernel<<<dim3(128, 1, 48), 128>>>(offF, share, x,                   // 2
                                                pofi, psi, pcomb);
    conv_om_em1_kernel<<<dim3(64, 4, 5), 512, SMEM_CONV>>>(                       // 3: om + em1
        pofi, psi, pwom, pwe1, b_om, b_em1, pom, pe1i);
    conv_em2_kernel<<<dim3(64, 4, 2), 512, SMEM_CONV>>>(                          // 4: em2
        pe1i, pwe2, b_em2, pem);
    deform_kernel<<<dim3(128, 32), 256>>>(w_dc, b_dc, pcomb, out);                // 5

    (void)in_sizes; (void)n_in; (void)out_size;
}

// round 15
// speedup vs baseline: 1.1085x; 1.1085x over previous
#include <cuda_runtime.h>
#include <cuda_fp16.h>
#include <cstdint>
#include <mma.h>

using namespace nvcuda;
typedef unsigned long long ull;

#define Bn 4
#define Hh 128
#define Wwidth 128
#define HW (128*128)

// ---------------- packed fp32x2 helpers ------------------------------------
__device__ __forceinline__ ull pk(float lo, float hi) {
    ull r; asm("mov.b64 %0, {%1,%2};" : "=l"(r) : "f"(lo), "f"(hi)); return r;
}
__device__ __forceinline__ void upk(ull v, float& lo, float& hi) {
    asm("mov.b64 {%0,%1}, %2;" : "=f"(lo), "=f"(hi) : "l"(v));
}
__device__ __forceinline__ ull ffma2(ull a, ull b, ull c) {
    ull d; asm("fma.rn.f32x2 %0, %1, %2, %3;" : "=l"(d) : "l"(a), "l"(b), "l"(c)); return d;
}

// -------- scratch --------
__device__ float  g_om [Bn*216*HW];            // conv_om raw (fp32 NCHW)
__device__ float  g_em [Bn*72*HW];             // sigmoid(conv em2) fp32 NCHW
// conv-input channel-interleaved fp16 planes: [b][chunk16][h][w][ci16]
__device__ __half g_ofi[(size_t)Bn*64*HW];     // offset_feat
__device__ __half g_si [(size_t)Bn*64*HW];     // share (em1 conv input)
__device__ __half g_e1i[(size_t)Bn*64*HW];     // em1 output (em2 conv input)
// combined sampling plane: [b][g8][h][w][x8|share8] fp16 (32 B per pixel)
__device__ __half g_comb[(size_t)Bn*8*HW*16];
// packed fp16 weights [CoP][Ktot], K index = (chunk*9+tap)*16+ci
__device__ __half g_wom[256*576];
__device__ __half g_we1[64*1152];
__device__ __half g_we2[128*576];

// ---------------------------------------------------------------------------
// fused weight pack: all three weight tensors in one launch.
// ---------------------------------------------------------------------------
__global__ void pack_all_kernel(const float* __restrict__ w0,
                                const float* __restrict__ w1,
                                const float* __restrict__ w2,
                                __half* __restrict__ d0,
                                __half* __restrict__ d1,
                                __half* __restrict__ d2)
{
    const int t = blockIdx.y;
    const float* w; __half* d; int Co, CoP, CIN;
    if (t == 0)      { w = w0; d = d0; Co = 216; CoP = 256; CIN = 64; }
    else if (t == 1) { w = w1; d = d1; Co = 64;  CoP = 64;  CIN = 128; }
    else             { w = w2; d = d2; Co = 72;  CoP = 128; CIN = 64; }

    int idx = blockIdx.x * 256 + threadIdx.x;
    int Ktot = CIN * 9;
    if (idx >= CoP * Ktot) return;
    int co = idx / Ktot, k = idx % Ktot;
    int chunk = k / 144, rem = k % 144, tap = rem / 16, ci = rem % 16;
    int cin = chunk * 16 + ci;
    float v = (co < Co) ? w[((size_t)co * CIN + cin) * 9 + tap] : 0.f;
    d[idx] = __float2half_rn(v);
}

// ---------------------------------------------------------------------------
// fused input transpose. t=0: offF -> ofi. t=1: share -> si AND comb[+8].
// t=2: x -> comb[+0].
// ---------------------------------------------------------------------------
__global__ void __launch_bounds__(128) split_all_kernel(
    const float* __restrict__ in0, const float* __restrict__ in1,
    const float* __restrict__ in2,
    __half* __restrict__ ofi, __half* __restrict__ si, __half* __restrict__ comb)
{
    const int px = threadIdx.x;
    const int h = blockIdx.x;
    const int z = blockIdx.z;
    const int t = z >> 4;
    const int b = (z >> 2) & 3, chunk = z & 3;
    const float* in = (t == 0) ? in0 : (t == 1) ? in1 : in2;

    const float* src = in + (size_t)(b * 64 + chunk * 16) * HW + h * Wwidth + px;
    __half hv[16];
    #pragma unroll
    for (int ci = 0; ci < 16; ci++) hv[ci] = __float2half_rn(src[(size_t)ci * HW]);

    const size_t pix = (size_t)h * Wwidth + px;
    if (t == 0 || t == 1) {
        __half* o = (t == 0) ? ofi : si;
        size_t off = (((size_t)(b * 4 + chunk) * Hh + h) * Wwidth + px) * 16;
        ((uint4*)(o + off))[0] = ((const uint4*)hv)[0];
        ((uint4*)(o + off))[1] = ((const uint4*)hv)[1];
    }
    if (t == 1 || t == 2) {
        // comb record: [b][g][pix][16]; x at +0, share at +8
        int lane = (t == 2) ? 0 : 8;
        size_t o0 = (((size_t)(b * 8 + chunk * 2)     * HW) + pix) * 16 + lane;
        size_t o1 = (((size_t)(b * 8 + chunk * 2 + 1) * HW) + pix) * 16 + lane;
        *(uint4*)(comb + o0) = ((const uint4*)hv)[0];
        *(uint4*)(comb + o1) = ((const uint4*)hv)[1];
    }
}

// ---------------------------------------------------------------------------
// Tensor-core implicit-GEMM 3x3 conv, pad=1, fp16 single-pass (fp32 accum).
// R9 proven form: block = 2 rows x 128 px x 64 co, 512 threads = 16 warps,
// warp tile 32co x 32px. All parameters are template constants.
// ---------------------------------------------------------------------------
#define XSZ2 (4*132*16)                 // halves, 2-row input tile
#define SMEM_CONV (XSZ2*2 + 64*144*2)   // 35328 B

template<int CHUNKS, int C0CHUNKS, int ACT>
__global__ void __launch_bounds__(512) conv2_kernel(
    const __half* __restrict__ x0, const __half* __restrict__ x1,
    const __half* __restrict__ wA, const float* __restrict__ bias,
    float* __restrict__ outF, __half* __restrict__ outH, int Co)
{
    extern __shared__ __align__(16) char smem_raw[];
    __half* s_x = (__half*)smem_raw;                    // [4][132][16]
    __half* s_w = (__half*)(smem_raw + XSZ2 * 2);       // [64][144]
    float*  sEp = (float*)smem_raw;                     // [64][136] (aliased, per row)

    const int tid = threadIdx.x;
    const int h2 = blockIdx.x, b = blockIdx.y, coTile = blockIdx.z;
    const int h0 = h2 * 2;
    const int warp = tid >> 5;
    const int rowSub = warp >> 3;
    const int coSub  = (warp >> 2) & 1;
    const int nSub   = warp & 3;
    const int Ktot   = CHUNKS * 144;

    wmma::fragment<wmma::accumulator, 16, 16, 16, float> acc[2][2];
    #pragma unroll
    for (int cf = 0; cf < 2; cf++)
        #pragma unroll
        for (int nf = 0; nf < 2; nf++) wmma::fill_fragment(acc[cf][nf], 0.f);

    if (tid < 32) {
        int r = tid >> 3, q = tid & 7;
        const int cols[4] = {0, 129, 130, 131};
        int scol = cols[q >> 1];
        uint4 z = {0, 0, 0, 0};
        ((uint4*)(s_x + (r * 132 + scol) * 16))[q & 1] = z;
    }

    for (int chunk = 0; chunk < CHUNKS; chunk++) {
        const __half* base;
        if (chunk < C0CHUNKS)
            base = x0 + ((size_t)b * C0CHUNKS + chunk) * HW * 16;
        else
            base = x1 + ((size_t)b * (CHUNKS - C0CHUNKS) + (chunk - C0CHUNKS)) * HW * 16;
        for (int u = tid; u < 1024; u += 512) {
            int r = u >> 8, c = u & 255;
            int row = h0 - 1 + r;
            uint4 v = {0, 0, 0, 0};
            if (row >= 0 && row < Hh)
                v = *(const uint4*)(base + (size_t)row * 2048 + c * 8);
            *(uint4*)(s_x + (r * 132 + 1) * 16 + c * 8) = v;
        }
        for (int u = tid; u < 1152; u += 512) {
            int co = u / 18, c = u - co * 18;
            *(uint4*)(s_w + co * 144 + c * 8) =
                *(const uint4*)(wA + (size_t)(coTile * 64 + co) * Ktot + chunk * 144 + c * 8);
        }
        __syncthreads();

        #pragma unroll
        for (int tap = 0; tap < 9; tap++) {
            const int dr = tap / 3, dc = tap % 3;
            wmma::fragment<wmma::matrix_a, 16, 16, 16, __half, wmma::row_major> af[2];
            #pragma unroll
            for (int cf = 0; cf < 2; cf++)
                wmma::load_matrix_sync(af[cf], s_w + (coSub * 32 + cf * 16) * 144 + tap * 16, 144);
            wmma::fragment<wmma::matrix_b, 16, 16, 16, __half, wmma::col_major> bfr[2];
            #pragma unroll
            for (int nf = 0; nf < 2; nf++) {
                int scol = nSub * 32 + nf * 16 + dc;
                wmma::load_matrix_sync(bfr[nf], s_x + ((rowSub + dr) * 132 + scol) * 16, 16);
            }
            #pragma unroll
            for (int cf = 0; cf < 2; cf++)
                #pragma unroll
                for (int nf = 0; nf < 2; nf++)
                    wmma::mma_sync(acc[cf][nf], af[cf], bfr[nf], acc[cf][nf]);
        }
        __syncthreads();
    }

    #pragma unroll
    for (int r = 0; r < 2; r++) {
        if (rowSub == r) {
            #pragma unroll
            for (int cf = 0; cf < 2; cf++)
                #pragma unroll
                for (int nf = 0; nf < 2; nf++)
                    wmma::store_matrix_sync(
                        sEp + (coSub * 32 + cf * 16) * 136 + (nSub * 32 + nf * 16),
                        acc[cf][nf], 136, wmma::mem_row_major);
        }
        __syncthreads();

        const int h = h0 + r;
        const int px = tid & 127;
        if (ACT == 1) {
            int ch = tid >> 7;
            __half hv[16];
            #pragma unroll
            for (int ci = 0; ci < 16; ci++) {
                int co = ch * 16 + ci;
                float v = sEp[co * 136 + px] + bias[co];
                v = (v >= 0.f) ? v : 0.1f * v;
                hv[ci] = __float2half_rn(v);
            }
            size_t o = (((size_t)(b * 4 + ch) * Hh + h) * Wwidth + px) * 16;
            ((uint4*)(outH + o))[0] = ((const uint4*)hv)[0];
            ((uint4*)(outH + o))[1] = ((const uint4*)hv)[1];
        } else {
            for (int co = tid >> 7; co < 64; co += 4) {
                int oc = coTile * 64 + co;
                if (oc < Co) {
                    float v = sEp[co * 136 + px] + bias[oc];
                    if (ACT == 2) v = 1.f / (1.f + __expf(-v));
                    outF[((size_t)b * Co + oc) * HW + h * Wwidth + px] = v;
                }
            }
        }
        __syncthreads();
    }
}

// ---------------------------------------------------------------------------
// Both deformable convs: warps 0-3 -> x_deform, warps 4-7 -> share_deform.
// x and share sample the SAME combined plane so corner cache lines are
// shared between the two halves (128 B record covers both tensors).
// ---------------------------------------------------------------------------
__global__ void __launch_bounds__(256) deform_kernel(
    const float* __restrict__ w_dc, const float* __restrict__ b_dc,
    const __half* __restrict__ comb, float* __restrict__ out)
{
    __shared__ __align__(16) float s_w[8][9][8];
    __shared__ float s_b[8];

    const int tid  = threadIdx.x;
    const int half = tid >> 7;
    const int w    = tid & 127;
    const int h    = blockIdx.x;
    const int bg   = blockIdx.y;
    const int b    = bg >> 3, g = bg & 7;

    for (int e = tid; e < 576; e += 256) {
        int c = e / 72, r = e % 72;
        int kk = r / 8, co = r % 8;
        s_w[c][kk][co] = w_dc[((size_t)(g * 8 + co) * 8 + c) * 9 + kk];
    }
    if (tid < 8) s_b[tid] = b_dc[g * 8 + tid];
    __syncthreads();

    const int pix = h * Wwidth + w;
    const float* omB = g_om + (size_t)b * 216 * HW + pix;
    const float* emB = g_em + (size_t)b * 72 * HW + pix;
    const __half* src = comb + ((size_t)(b * 8 + g) * HW) * 16 + half * 8;

    ull acc[4];
    #pragma unroll
    for (int j = 0; j < 4; j++) acc[j] = 0ull;

    #pragma unroll
    for (int kk = 0; kk < 9; kk++) {
        const int kh = kk / 3, kw = kk % 3;
        float dy = omB[(size_t)(g * 18 + 2 * kk) * HW];
        float dx = omB[(size_t)(g * 18 + 2 * kk + 1) * HW];
        float mask;
        if (half == 0) {
            float mz = omB[(size_t)(144 + g * 9 + kk) * HW];
            mask = 1.f / (1.f + __expf(-mz));
        } else {
            mask = emB[(size_t)(g * 9 + kk) * HW];
        }

        float py = (float)(h - 1 + kh) + dy;
        float px = (float)(w - 1 + kw) + dx;
        float fy = floorf(py), fx = floorf(px);
        float ly = py - fy, lx = px - fx;
        int y0 = (int)fy, x0 = (int)fx;
        int y1 = y0 + 1, x1 = x0 + 1;

        float w00 = (1.f - ly) * (1.f - lx);
        float w01 = (1.f - ly) * lx;
        float w10 = ly * (1.f - lx);
        float w11 = ly * lx;
        if (y0 < 0 || y0 >= Hh)     { w00 = 0.f; w01 = 0.f; }
        if (y1 < 0 || y1 >= Hh)     { w10 = 0.f; w11 = 0.f; }
        if (x0 < 0 || x0 >= Wwidth) { w00 = 0.f; w10 = 0.f; }
        if (x1 < 0 || x1 >= Wwidth) { w01 = 0.f; w11 = 0.f; }

        int cy0 = min(max(y0, 0), Hh - 1),     cy1 = min(max(y1, 0), Hh - 1);
        int cx0 = min(max(x0, 0), Wwidth - 1), cx1 = min(max(x1, 0), Wwidth - 1);
        int i00 = (cy0 * Wwidth + cx0) * 16, i01 = (cy0 * Wwidth + cx1) * 16;
        int i10 = (cy1 * Wwidth + cx0) * 16, i11 = (cy1 * Wwidth + cx1) * 16;

        float4 r00 = *(const float4*)(src + i00);
        float4 r01 = *(const float4*)(src + i01);
        float4 r10 = *(const float4*)(src + i10);
        float4 r11 = *(const float4*)(src + i11);
        const __half2* h00 = (const __half2*)&r00;
        const __half2* h01 = (const __half2*)&r01;
        const __half2* h10 = (const __half2*)&r10;
        const __half2* h11 = (const __half2*)&r11;

        float vv[8];
        #pragma unroll
        for (int j2 = 0; j2 < 4; j2++) {
            float2 f00 = __half22float2(h00[j2]);
            float2 f01 = __half22float2(h01[j2]);
            float2 f10 = __half22float2(h10[j2]);
            float2 f11 = __half22float2(h11[j2]);
            vv[2 * j2]     = (w00 * f00.x + w01 * f01.x + w10 * f10.x + w11 * f11.x) * mask;
            vv[2 * j2 + 1] = (w00 * f00.y + w01 * f01.y + w10 * f10.y + w11 * f11.y) * mask;
        }

        #pragma unroll
        for (int c = 0; c < 8; c++) {
            ull xs = pk(vv[c], vv[c]);
            #pragma unroll
            for (int j = 0; j < 4; j++) {
                ull wp = *(const ull*)&s_w[c][kk][2 * j];
                acc[j] = ffma2(xs, wp, acc[j]);
            }
        }
    }

    float* ob = out + (size_t)half * Bn * 64 * HW + (size_t)(b * 64 + g * 8) * HW + pix;
    #pragma unroll
    for (int j = 0; j < 4; j++) {
        float v0, v1;
        upk(acc[j], v0, v1);
        ob[(size_t)(2 * j) * HW]     = v0 + s_b[2 * j];
        ob[(size_t)(2 * j + 1) * HW] = v1 + s_b[2 * j + 1];
    }
}

// ---------------------------------------------------------------------------
extern "C" void kernel_launch(void* const* d_in, const int* in_sizes, int n_in,
                              void* d_out, int out_size)
{
    const float* x      = (const float*)d_in[0];
    const float* share  = (const float*)d_in[1];
    const float* offF   = (const float*)d_in[2];
    const float* w_om   = (const float*)d_in[3];
    const float* b_om   = (const float*)d_in[4];
    const float* w_em1  = (const float*)d_in[5];
    const float* b_em1  = (const float*)d_in[6];
    const float* w_em2  = (const float*)d_in[7];
    const float* b_em2  = (const float*)d_in[8];
    const float* w_dc   = (const float*)d_in[9];
    const float* b_dc   = (const float*)d_in[10];
    float* out = (float*)d_out;

    float *pom, *pem;
    __half *psi, *pofi, *pe1i, *pcomb, *pwom, *pwe1, *pwe2;
    cudaGetSymbolAddress((void**)&pom,   g_om);
    cudaGetSymbolAddress((void**)&pem,   g_em);
    cudaGetSymbolAddress((void**)&psi,   g_si);
    cudaGetSymbolAddress((void**)&pofi,  g_ofi);
    cudaGetSymbolAddress((void**)&pe1i,  g_e1i);
    cudaGetSymbolAddress((void**)&pcomb, g_comb);
    cudaGetSymbolAddress((void**)&pwom,  g_wom);
    cudaGetSymbolAddress((void**)&pwe1,  g_we1);
    cudaGetSymbolAddress((void**)&pwe2,  g_we2);

    cudaFuncSetAttribute(conv2_kernel<4, 4, 0>,
                         cudaFuncAttributeMaxDynamicSharedMemorySize, SMEM_CONV);
    cudaFuncSetAttribute(conv2_kernel<8, 4, 1>,
                         cudaFuncAttributeMaxDynamicSharedMemorySize, SMEM_CONV);
    cudaFuncSetAttribute(conv2_kernel<4, 4, 2>,
                         cudaFuncAttributeMaxDynamicSharedMemorySize, SMEM_CONV);

    // 6 launches; ncu profiles launch #6 -> deform_kernel (comb layout)
    pack_all_kernel<<<dim3(576, 3), 256>>>(w_om, w_em1, w_em2,                    // 1
                                           pwom, pwe1, pwe2);
    split_all_kernel<<<dim3(128, 1, 48), 128>>>(offF, share, x,                   // 2
                                                pofi, psi, pcomb);
    conv2_kernel<4, 4, 0><<<dim3(64, 4, 4), 512, SMEM_CONV>>>(                    // 3: om
        pofi, pofi, pwom, b_om, pom, nullptr, 216);
    conv2_kernel<8, 4, 1><<<dim3(64, 4, 1), 512, SMEM_CONV>>>(                    // 4: em1
        psi, pofi, pwe1, b_em1, nullptr, pe1i, 64);
    conv2_kernel<4, 4, 2><<<dim3(64, 4, 2), 512, SMEM_CONV>>>(                    // 5: em2
        pe1i, pe1i, pwe2, b_em2, pem, nullptr, 72);
    deform_kernel<<<dim3(128, 32), 256>>>(w_dc, b_dc, pcomb, out);                // 6

    (void)in_sizes; (void)n_in; (void)out_size;
}

// round 16
// speedup vs baseline: 1.1383x; 1.0269x over previous
#include <cuda_runtime.h>
#include <cuda_fp16.h>
#include <cstdint>
#include <mma.h>

using namespace nvcuda;
typedef unsigned long long ull;

#define Bn 4
#define Hh 128
#define Wwidth 128
#define HW (128*128)

// ---------------- packed fp32x2 helpers ------------------------------------
__device__ __forceinline__ ull pk(float lo, float hi) {
    ull r; asm("mov.b64 %0, {%1,%2};" : "=l"(r) : "f"(lo), "f"(hi)); return r;
}
__device__ __forceinline__ void upk(ull v, float& lo, float& hi) {
    asm("mov.b64 {%0,%1}, %2;" : "=f"(lo), "=f"(hi) : "l"(v));
}
__device__ __forceinline__ ull ffma2(ull a, ull b, ull c) {
    ull d; asm("fma.rn.f32x2 %0, %1, %2, %3;" : "=l"(d) : "l"(a), "l"(b), "l"(c)); return d;
}

// -------- scratch --------
__device__ float  g_om [Bn*216*HW];            // conv_om raw (fp32 NCHW)
__device__ float  g_em [Bn*72*HW];             // sigmoid(conv em2) fp32 NCHW
// conv-input channel-interleaved fp16 planes: [b][chunk16][h][w][ci16]
__device__ __half g_ofi[(size_t)Bn*64*HW];     // offset_feat
__device__ __half g_si [(size_t)Bn*64*HW];     // share (em1 conv input)
__device__ __half g_e1i[(size_t)Bn*64*HW];     // em1 output (em2 conv input)
// combined sampling plane: [b][g8][h][w][x8|share8] fp16 (32 B per pixel)
__device__ __half g_comb[(size_t)Bn*8*HW*16];
// packed fp16 weights [CoP][Ktot], K index = (chunk*9+tap)*16+ci
__device__ __half g_wom[256*576];
__device__ __half g_we1[64*1152];
__device__ __half g_we2[128*576];

// ---------------------------------------------------------------------------
// prep kernel: fused input transpose (blocks 0..3071, 2 rows each) +
// weight pack (blocks 3072..4223). 256 threads.
// ---------------------------------------------------------------------------
#define SPLIT_BLOCKS 3072
#define PACK_OM_ELEMS  (256*576)
#define PACK_WE1_ELEMS (64*1152)
#define PACK_WE2_ELEMS (128*576)
#define PACK_BLOCKS ((PACK_OM_ELEMS + PACK_WE1_ELEMS + PACK_WE2_ELEMS) / 256)  // 1152

__global__ void __launch_bounds__(256) prep_kernel(
    const float* __restrict__ xIn, const float* __restrict__ shareIn,
    const float* __restrict__ offIn,
    const float* __restrict__ w0, const float* __restrict__ w1,
    const float* __restrict__ w2,
    __half* __restrict__ ofi, __half* __restrict__ si, __half* __restrict__ comb,
    __half* __restrict__ d0, __half* __restrict__ d1, __half* __restrict__ d2)
{
    const int bid = blockIdx.x;
    const int tid = threadIdx.x;

    if (bid < SPLIT_BLOCKS) {
        // transpose role: slice z = bid/64, h = (bid%64)*2 + (tid>>7)
        const int z = bid >> 6;
        const int h = ((bid & 63) << 1) + (tid >> 7);
        const int px = tid & 127;
        const int t = z >> 4;                 // 0: offF, 1: share, 2: x
        const int b = (z >> 2) & 3, chunk = z & 3;
        const float* in = (t == 0) ? offIn : (t == 1) ? shareIn : xIn;

        const float* src = in + (size_t)(b * 64 + chunk * 16) * HW + h * Wwidth + px;
        __half hv[16];
        #pragma unroll
        for (int ci = 0; ci < 16; ci++) hv[ci] = __float2half_rn(src[(size_t)ci * HW]);

        const size_t pix = (size_t)h * Wwidth + px;
        if (t == 0 || t == 1) {
            __half* o = (t == 0) ? ofi : si;
            size_t off = (((size_t)(b * 4 + chunk) * Hh + h) * Wwidth + px) * 16;
            ((uint4*)(o + off))[0] = ((const uint4*)hv)[0];
            ((uint4*)(o + off))[1] = ((const uint4*)hv)[1];
        }
        if (t == 1 || t == 2) {
            int lane = (t == 2) ? 0 : 8;      // x at +0, share at +8
            size_t o0 = (((size_t)(b * 8 + chunk * 2)     * HW) + pix) * 16 + lane;
            size_t o1 = (((size_t)(b * 8 + chunk * 2 + 1) * HW) + pix) * 16 + lane;
            *(uint4*)(comb + o0) = ((const uint4*)hv)[0];
            *(uint4*)(comb + o1) = ((const uint4*)hv)[1];
        }
        return;
    }

    // pack role
    int idx = (bid - SPLIT_BLOCKS) * 256 + tid;
    const float* w; __half* d; int Co, CIN;
    if (idx < PACK_OM_ELEMS) {
        w = w0; d = d0; Co = 216; CIN = 64;
    } else if (idx < PACK_OM_ELEMS + PACK_WE1_ELEMS) {
        idx -= PACK_OM_ELEMS;
        w = w1; d = d1; Co = 64; CIN = 128;
    } else {
        idx -= PACK_OM_ELEMS + PACK_WE1_ELEMS;
        w = w2; d = d2; Co = 72; CIN = 64;
    }
    int Ktot = CIN * 9;
    int co = idx / Ktot, k = idx % Ktot;
    int chunk = k / 144, rem = k % 144, tap = rem / 16, ci = rem % 16;
    int cin = chunk * 16 + ci;
    float v = (co < Co) ? w[((size_t)co * CIN + cin) * 9 + tap] : 0.f;
    d[idx] = __float2half_rn(v);
}

// ---------------------------------------------------------------------------
// Conv body (R9 proven form): block = 2 rows x 128 px x 64 co, 512 threads,
// warp tile 32co x 32px. Fully templated; inlined into specialized branches.
// ---------------------------------------------------------------------------
#define XSZ2 (4*132*16)                 // halves, 2-row input tile
#define SMEM_CONV (XSZ2*2 + 64*144*2)   // 35328 B

template<int CHUNKS, int C0CHUNKS, int ACT>
__device__ __forceinline__ void conv_body(
    const __half* __restrict__ x0, const __half* __restrict__ x1,
    const __half* __restrict__ wA, const float* __restrict__ bias,
    float* __restrict__ outF, __half* __restrict__ outH, int Co, int coTile,
    char* smem_raw)
{
    __half* s_x = (__half*)smem_raw;                    // [4][132][16]
    __half* s_w = (__half*)(smem_raw + XSZ2 * 2);       // [64][144]
    float*  sEp = (float*)smem_raw;                     // [64][136] (aliased)

    const int tid = threadIdx.x;
    const int h2 = blockIdx.x, b = blockIdx.y;
    const int h0 = h2 * 2;
    const int warp = tid >> 5;
    const int rowSub = warp >> 3;
    const int coSub  = (warp >> 2) & 1;
    const int nSub   = warp & 3;
    const int Ktot   = CHUNKS * 144;

    wmma::fragment<wmma::accumulator, 16, 16, 16, float> acc[2][2];
    #pragma unroll
    for (int cf = 0; cf < 2; cf++)
        #pragma unroll
        for (int nf = 0; nf < 2; nf++) wmma::fill_fragment(acc[cf][nf], 0.f);

    if (tid < 32) {
        int r = tid >> 3, q = tid & 7;
        const int cols[4] = {0, 129, 130, 131};
        int scol = cols[q >> 1];
        uint4 z = {0, 0, 0, 0};
        ((uint4*)(s_x + (r * 132 + scol) * 16))[q & 1] = z;
    }

    for (int chunk = 0; chunk < CHUNKS; chunk++) {
        const __half* base;
        if (chunk < C0CHUNKS)
            base = x0 + ((size_t)b * C0CHUNKS + chunk) * HW * 16;
        else
            base = x1 + ((size_t)b * (CHUNKS - C0CHUNKS) + (chunk - C0CHUNKS)) * HW * 16;
        for (int u = tid; u < 1024; u += 512) {
            int r = u >> 8, c = u & 255;
            int row = h0 - 1 + r;
            uint4 v = {0, 0, 0, 0};
            if (row >= 0 && row < Hh)
                v = *(const uint4*)(base + (size_t)row * 2048 + c * 8);
            *(uint4*)(s_x + (r * 132 + 1) * 16 + c * 8) = v;
        }
        for (int u = tid; u < 1152; u += 512) {
            int co = u / 18, c = u - co * 18;
            *(uint4*)(s_w + co * 144 + c * 8) =
                *(const uint4*)(wA + (size_t)(coTile * 64 + co) * Ktot + chunk * 144 + c * 8);
        }
        __syncthreads();

        #pragma unroll
        for (int tap = 0; tap < 9; tap++) {
            const int dr = tap / 3, dc = tap % 3;
            wmma::fragment<wmma::matrix_a, 16, 16, 16, __half, wmma::row_major> af[2];
            #pragma unroll
            for (int cf = 0; cf < 2; cf++)
                wmma::load_matrix_sync(af[cf], s_w + (coSub * 32 + cf * 16) * 144 + tap * 16, 144);
            wmma::fragment<wmma::matrix_b, 16, 16, 16, __half, wmma::col_major> bfr[2];
            #pragma unroll
            for (int nf = 0; nf < 2; nf++) {
                int scol = nSub * 32 + nf * 16 + dc;
                wmma::load_matrix_sync(bfr[nf], s_x + ((rowSub + dr) * 132 + scol) * 16, 16);
            }
            #pragma unroll
            for (int cf = 0; cf < 2; cf++)
                #pragma unroll
                for (int nf = 0; nf < 2; nf++)
                    wmma::mma_sync(acc[cf][nf], af[cf], bfr[nf], acc[cf][nf]);
        }
        __syncthreads();
    }

    #pragma unroll
    for (int r = 0; r < 2; r++) {
        if (rowSub == r) {
            #pragma unroll
            for (int cf = 0; cf < 2; cf++)
                #pragma unroll
                for (int nf = 0; nf < 2; nf++)
                    wmma::store_matrix_sync(
                        sEp + (coSub * 32 + cf * 16) * 136 + (nSub * 32 + nf * 16),
                        acc[cf][nf], 136, wmma::mem_row_major);
        }
        __syncthreads();

        const int h = h0 + r;
        const int px = tid & 127;
        if (ACT == 1) {
            int ch = tid >> 7;
            __half hv[16];
            #pragma unroll
            for (int ci = 0; ci < 16; ci++) {
                int co = ch * 16 + ci;
                float v = sEp[co * 136 + px] + bias[co];
                v = (v >= 0.f) ? v : 0.1f * v;
                hv[ci] = __float2half_rn(v);
            }
            size_t o = (((size_t)(b * 4 + ch) * Hh + h) * Wwidth + px) * 16;
            ((uint4*)(outH + o))[0] = ((const uint4*)hv)[0];
            ((uint4*)(outH + o))[1] = ((const uint4*)hv)[1];
        } else {
            for (int co = tid >> 7; co < 64; co += 4) {
                int oc = coTile * 64 + co;
                if (oc < Co) {
                    float v = sEp[co * 136 + px] + bias[oc];
                    if (ACT == 2) v = 1.f / (1.f + __expf(-v));
                    outF[((size_t)b * Co + oc) * HW + h * Wwidth + px] = v;
                }
            }
        }
        __syncthreads();
    }
}

// Merged om + em1: z=0 -> em1 (longest blocks first), z=1..4 -> om tiles.
// Each branch is a fully specialized template instantiation.
__global__ void __launch_bounds__(512) conv_om_em1_kernel(
    const __half* __restrict__ ofi, const __half* __restrict__ si,
    const __half* __restrict__ wom, const __half* __restrict__ we1,
    const float* __restrict__ b_om, const float* __restrict__ b_em1,
    float* __restrict__ omOut, __half* __restrict__ e1Out)
{
    extern __shared__ __align__(16) char smem_raw[];
    if (blockIdx.z == 0)
        conv_body<8, 4, 1>(si, ofi, we1, b_em1, nullptr, e1Out, 64, 0, smem_raw);
    else
        conv_body<4, 4, 0>(ofi, ofi, wom, b_om, omOut, nullptr, 216,
                           blockIdx.z - 1, smem_raw);
}

__global__ void __launch_bounds__(512) conv_em2_kernel(
    const __half* __restrict__ e1i, const __half* __restrict__ we2,
    const float* __restrict__ b_em2, float* __restrict__ emOut)
{
    extern __shared__ __align__(16) char smem_raw[];
    conv_body<4, 4, 2>(e1i, e1i, we2, b_em2, emOut, nullptr, 72,
                       blockIdx.z, smem_raw);
}

// ---------------------------------------------------------------------------
// Both deformable convs: warps 0-3 -> x_deform, warps 4-7 -> share_deform.
// x and share sample the SAME combined plane (corner lines shared).
// ---------------------------------------------------------------------------
__global__ void __launch_bounds__(256) deform_kernel(
    const float* __restrict__ w_dc, const float* __restrict__ b_dc,
    const __half* __restrict__ comb, float* __restrict__ out)
{
    __shared__ __align__(16) float s_w[8][9][8];
    __shared__ float s_b[8];

    const int tid  = threadIdx.x;
    const int half = tid >> 7;
    const int w    = tid & 127;
    const int h    = blockIdx.x;
    const int bg   = blockIdx.y;
    const int b    = bg >> 3, g = bg & 7;

    for (int e = tid; e < 576; e += 256) {
        int c = e / 72, r = e % 72;
        int kk = r / 8, co = r % 8;
        s_w[c][kk][co] = w_dc[((size_t)(g * 8 + co) * 8 + c) * 9 + kk];
    }
    if (tid < 8) s_b[tid] = b_dc[g * 8 + tid];
    __syncthreads();

    const int pix = h * Wwidth + w;
    const float* omB = g_om + (size_t)b * 216 * HW + pix;
    const float* emB = g_em + (size_t)b * 72 * HW + pix;
    const __half* src = comb + ((size_t)(b * 8 + g) * HW) * 16 + half * 8;

    ull acc[4];
    #pragma unroll
    for (int j = 0; j < 4; j++) acc[j] = 0ull;

    #pragma unroll
    for (int kk = 0; kk < 9; kk++) {
        const int kh = kk / 3, kw = kk % 3;
        float dy = omB[(size_t)(g * 18 + 2 * kk) * HW];
        float dx = omB[(size_t)(g * 18 + 2 * kk + 1) * HW];
        float mask;
        if (half == 0) {
            float mz = omB[(size_t)(144 + g * 9 + kk) * HW];
            mask = 1.f / (1.f + __expf(-mz));
        } else {
            mask = emB[(size_t)(g * 9 + kk) * HW];
        }

        float py = (float)(h - 1 + kh) + dy;
        float px = (float)(w - 1 + kw) + dx;
        float fy = floorf(py), fx = floorf(px);
        float ly = py - fy, lx = px - fx;
        int y0 = (int)fy, x0 = (int)fx;
        int y1 = y0 + 1, x1 = x0 + 1;

        float w00 = (1.f - ly) * (1.f - lx);
        float w01 = (1.f - ly) * lx;
        float w10 = ly * (1.f - lx);
        float w11 = ly * lx;
        if (y0 < 0 || y0 >= Hh)     { w00 = 0.f; w01 = 0.f; }
        if (y1 < 0 || y1 >= Hh)     { w10 = 0.f; w11 = 0.f; }
        if (x0 < 0 || x0 >= Wwidth) { w00 = 0.f; w10 = 0.f; }
        if (x1 < 0 || x1 >= Wwidth) { w01 = 0.f; w11 = 0.f; }

        int cy0 = min(max(y0, 0), Hh - 1),     cy1 = min(max(y1, 0), Hh - 1);
        int cx0 = min(max(x0, 0), Wwidth - 1), cx1 = min(max(x1, 0), Wwidth - 1);
        int i00 = (cy0 * Wwidth + cx0) * 16, i01 = (cy0 * Wwidth + cx1) * 16;
        int i10 = (cy1 * Wwidth + cx0) * 16, i11 = (cy1 * Wwidth + cx1) * 16;

        float4 r00 = *(const float4*)(src + i00);
        float4 r01 = *(const float4*)(src + i01);
        float4 r10 = *(const float4*)(src + i10);
        float4 r11 = *(const float4*)(src + i11);
        const __half2* h00 = (const __half2*)&r00;
        const __half2* h01 = (const __half2*)&r01;
        const __half2* h10 = (const __half2*)&r10;
        const __half2* h11 = (const __half2*)&r11;

        float vv[8];
        #pragma unroll
        for (int j2 = 0; j2 < 4; j2++) {
            float2 f00 = __half22float2(h00[j2]);
            float2 f01 = __half22float2(h01[j2]);
            float2 f10 = __half22float2(h10[j2]);
            float2 f11 = __half22float2(h11[j2]);
            vv[2 * j2]     = (w00 * f00.x + w01 * f01.x + w10 * f10.x + w11 * f11.x) * mask;
            vv[2 * j2 + 1] = (w00 * f00.y + w01 * f01.y + w10 * f10.y + w11 * f11.y) * mask;
        }

        #pragma unroll
        for (int c = 0; c < 8; c++) {
            ull xs = pk(vv[c], vv[c]);
            #pragma unroll
            for (int j = 0; j < 4; j++) {
                ull wp = *(const ull*)&s_w[c][kk][2 * j];
                acc[j] = ffma2(xs, wp, acc[j]);
            }
        }
    }

    float* ob = out + (size_t)half * Bn * 64 * HW + (size_t)(b * 64 + g * 8) * HW + pix;
    #pragma unroll
    for (int j = 0; j < 4; j++) {
        float v0, v1;
        upk(acc[j], v0, v1);
        ob[(size_t)(2 * j) * HW]     = v0 + s_b[2 * j];
        ob[(size_t)(2 * j + 1) * HW] = v1 + s_b[2 * j + 1];
    }
}

// ---------------------------------------------------------------------------
extern "C" void kernel_launch(void* const* d_in, const int* in_sizes, int n_in,
                              void* d_out, int out_size)
{
    const float* x      = (const float*)d_in[0];
    const float* share  = (const float*)d_in[1];
    const float* offF   = (const float*)d_in[2];
    const float* w_om   = (const float*)d_in[3];
    const float* b_om   = (const float*)d_in[4];
    const float* w_em1  = (const float*)d_in[5];
    const float* b_em1  = (const float*)d_in[6];
    const float* w_em2  = (const float*)d_in[7];
    const float* b_em2  = (const float*)d_in[8];
    const float* w_dc   = (const float*)d_in[9];
    const float* b_dc   = (const float*)d_in[10];
    float* out = (float*)d_out;

    float *pom, *pem;
    __half *psi, *pofi, *pe1i, *pcomb, *pwom, *pwe1, *pwe2;
    cudaGetSymbolAddress((void**)&pom,   g_om);
    cudaGetSymbolAddress((void**)&pem,   g_em);
    cudaGetSymbolAddress((void**)&psi,   g_si);
    cudaGetSymbolAddress((void**)&pofi,  g_ofi);
    cudaGetSymbolAddress((void**)&pe1i,  g_e1i);
    cudaGetSymbolAddress((void**)&pcomb, g_comb);
    cudaGetSymbolAddress((void**)&pwom,  g_wom);
    cudaGetSymbolAddress((void**)&pwe1,  g_we1);
    cudaGetSymbolAddress((void**)&pwe2,  g_we2);

    cudaFuncSetAttribute(conv_om_em1_kernel,
                         cudaFuncAttributeMaxDynamicSharedMemorySize, SMEM_CONV);
    cudaFuncSetAttribute(conv_em2_kernel,
                         cudaFuncAttributeMaxDynamicSharedMemorySize, SMEM_CONV);

    // 4 launches; ncu profiles launch #4 -> deform_kernel
    prep_kernel<<<SPLIT_BLOCKS + PACK_BLOCKS, 256>>>(                             // 1
        x, share, offF, w_om, w_em1, w_em2,
        pofi, psi, pcomb, pwom, pwe1, pwe2);
    conv_om_em1_kernel<<<dim3(64, 4, 5), 512, SMEM_CONV>>>(                       // 2
        pofi, psi, pwom, pwe1, b_om, b_em1, pom, pe1i);
    conv_em2_kernel<<<dim3(64, 4, 2), 512, SMEM_CONV>>>(                          // 3
        pe1i, pwe2, b_em2, pem);
    deform_kernel<<<dim3(128, 32), 256>>>(w_dc, b_dc, pcomb, out);                // 4

    (void)in_sizes; (void)n_in; (void)out_size;
}

// round 17
// speedup vs baseline: 1.1594x; 1.0185x over previous
#include <cuda_runtime.h>
#include <cuda_fp16.h>
#include <cstdint>
#include <mma.h>

using namespace nvcuda;
typedef unsigned long long ull;

#define Bn 4
#define Hh 128
#define Wwidth 128
#define HW (128*128)

// ---------------- packed fp32x2 helpers ------------------------------------
__device__ __forceinline__ ull pk(float lo, float hi) {
    ull r; asm("mov.b64 %0, {%1,%2};" : "=l"(r) : "f"(lo), "f"(hi)); return r;
}
__device__ __forceinline__ void upk(ull v, float& lo, float& hi) {
    asm("mov.b64 {%0,%1}, %2;" : "=f"(lo), "=f"(hi) : "l"(v));
}
__device__ __forceinline__ ull ffma2(ull a, ull b, ull c) {
    ull d; asm("fma.rn.f32x2 %0, %1, %2, %3;" : "=l"(d) : "l"(a), "l"(b), "l"(c)); return d;
}

// -------- scratch --------
__device__ float  g_om [Bn*216*HW];            // conv_om raw (fp32 NCHW)
__device__ float  g_em [Bn*72*HW];             // sigmoid(conv em2) fp32 NCHW
// conv-input channel-interleaved fp16 planes: [b][chunk16][h][w][ci16]
__device__ __half g_ofi[(size_t)Bn*64*HW];     // offset_feat
__device__ __half g_si [(size_t)Bn*64*HW];     // share (em1 conv input)
__device__ __half g_e1i[(size_t)Bn*64*HW];     // em1 output (em2 conv input)
// combined sampling plane: [b][g8][h][w][x8|share8] fp16 (32 B per pixel)
__device__ __half g_comb[(size_t)Bn*8*HW*16];
// packed fp16 weights [CoP][Ktot], K index = (chunk*9+tap)*16+ci
__device__ __half g_wom[256*576];
__device__ __half g_we1[64*1152];
__device__ __half g_we2[128*576];

// ---------------------------------------------------------------------------
// prep kernel: fused input transpose (blocks 0..3071, 2 rows each) +
// weight pack (blocks 3072..4223). 256 threads.
// ---------------------------------------------------------------------------
#define SPLIT_BLOCKS 3072
#define PACK_OM_ELEMS  (256*576)
#define PACK_WE1_ELEMS (64*1152)
#define PACK_WE2_ELEMS (128*576)
#define PACK_BLOCKS ((PACK_OM_ELEMS + PACK_WE1_ELEMS + PACK_WE2_ELEMS) / 256)  // 1152

__global__ void __launch_bounds__(256) prep_kernel(
    const float* __restrict__ xIn, const float* __restrict__ shareIn,
    const float* __restrict__ offIn,
    const float* __restrict__ w0, const float* __restrict__ w1,
    const float* __restrict__ w2,
    __half* __restrict__ ofi, __half* __restrict__ si, __half* __restrict__ comb,
    __half* __restrict__ d0, __half* __restrict__ d1, __half* __restrict__ d2)
{
    const int bid = blockIdx.x;
    const int tid = threadIdx.x;

    if (bid < SPLIT_BLOCKS) {
        const int z = bid >> 6;
        const int h = ((bid & 63) << 1) + (tid >> 7);
        const int px = tid & 127;
        const int t = z >> 4;                 // 0: offF, 1: share, 2: x
        const int b = (z >> 2) & 3, chunk = z & 3;
        const float* in = (t == 0) ? offIn : (t == 1) ? shareIn : xIn;

        const float* src = in + (size_t)(b * 64 + chunk * 16) * HW + h * Wwidth + px;
        __half hv[16];
        #pragma unroll
        for (int ci = 0; ci < 16; ci++) hv[ci] = __float2half_rn(src[(size_t)ci * HW]);

        const size_t pix = (size_t)h * Wwidth + px;
        if (t == 0 || t == 1) {
            __half* o = (t == 0) ? ofi : si;
            size_t off = (((size_t)(b * 4 + chunk) * Hh + h) * Wwidth + px) * 16;
            ((uint4*)(o + off))[0] = ((const uint4*)hv)[0];
            ((uint4*)(o + off))[1] = ((const uint4*)hv)[1];
        }
        if (t == 1 || t == 2) {
            int lane = (t == 2) ? 0 : 8;      // x at +0, share at +8
            size_t o0 = (((size_t)(b * 8 + chunk * 2)     * HW) + pix) * 16 + lane;
            size_t o1 = (((size_t)(b * 8 + chunk * 2 + 1) * HW) + pix) * 16 + lane;
            *(uint4*)(comb + o0) = ((const uint4*)hv)[0];
            *(uint4*)(comb + o1) = ((const uint4*)hv)[1];
        }
        return;
    }

    int idx = (bid - SPLIT_BLOCKS) * 256 + tid;
    const float* w; __half* d; int Co, CIN;
    if (idx < PACK_OM_ELEMS) {
        w = w0; d = d0; Co = 216; CIN = 64;
    } else if (idx < PACK_OM_ELEMS + PACK_WE1_ELEMS) {
        idx -= PACK_OM_ELEMS;
        w = w1; d = d1; Co = 64; CIN = 128;
    } else {
        idx -= PACK_OM_ELEMS + PACK_WE1_ELEMS;
        w = w2; d = d2; Co = 72; CIN = 64;
    }
    int Ktot = CIN * 9;
    int co = idx / Ktot, k = idx % Ktot;
    int chunk = k / 144, rem = k % 144, tap = rem / 16, ci = rem % 16;
    int cin = chunk * 16 + ci;
    float v = (co < Co) ? w[((size_t)co * CIN + cin) * 9 + tap] : 0.f;
    d[idx] = __float2half_rn(v);
}

// ---------------------------------------------------------------------------
// Conv body (R9 proven form): block = 2 rows x 128 px x 64 co, 512 threads,
// warp tile 32co x 32px. Fully templated; inlined into specialized branches.
// ---------------------------------------------------------------------------
#define XSZ2 (4*132*16)                 // halves, 2-row input tile
#define SMEM_CONV (XSZ2*2 + 64*144*2)   // 35328 B

template<int CHUNKS, int C0CHUNKS, int ACT>
__device__ __forceinline__ void conv_body(
    const __half* __restrict__ x0, const __half* __restrict__ x1,
    const __half* __restrict__ wA, const float* __restrict__ bias,
    float* __restrict__ outF, __half* __restrict__ outH, int Co, int coTile,
    char* smem_raw)
{
    __half* s_x = (__half*)smem_raw;                    // [4][132][16]
    __half* s_w = (__half*)(smem_raw + XSZ2 * 2);       // [64][144]
    float*  sEp = (float*)smem_raw;                     // [64][136] (aliased)

    const int tid = threadIdx.x;
    const int h2 = blockIdx.x, b = blockIdx.y;
    const int h0 = h2 * 2;
    const int warp = tid >> 5;
    const int rowSub = warp >> 3;
    const int coSub  = (warp >> 2) & 1;
    const int nSub   = warp & 3;
    const int Ktot   = CHUNKS * 144;

    wmma::fragment<wmma::accumulator, 16, 16, 16, float> acc[2][2];
    #pragma unroll
    for (int cf = 0; cf < 2; cf++)
        #pragma unroll
        for (int nf = 0; nf < 2; nf++) wmma::fill_fragment(acc[cf][nf], 0.f);

    if (tid < 32) {
        int r = tid >> 3, q = tid & 7;
        const int cols[4] = {0, 129, 130, 131};
        int scol = cols[q >> 1];
        uint4 z = {0, 0, 0, 0};
        ((uint4*)(s_x + (r * 132 + scol) * 16))[q & 1] = z;
    }

    for (int chunk = 0; chunk < CHUNKS; chunk++) {
        const __half* base;
        if (chunk < C0CHUNKS)
            base = x0 + ((size_t)b * C0CHUNKS + chunk) * HW * 16;
        else
            base = x1 + ((size_t)b * (CHUNKS - C0CHUNKS) + (chunk - C0CHUNKS)) * HW * 16;
        for (int u = tid; u < 1024; u += 512) {
            int r = u >> 8, c = u & 255;
            int row = h0 - 1 + r;
            uint4 v = {0, 0, 0, 0};
            if (row >= 0 && row < Hh)
                v = *(const uint4*)(base + (size_t)row * 2048 + c * 8);
            *(uint4*)(s_x + (r * 132 + 1) * 16 + c * 8) = v;
        }
        for (int u = tid; u < 1152; u += 512) {
            int co = u / 18, c = u - co * 18;
            *(uint4*)(s_w + co * 144 + c * 8) =
                *(const uint4*)(wA + (size_t)(coTile * 64 + co) * Ktot + chunk * 144 + c * 8);
        }
        __syncthreads();

        #pragma unroll
        for (int tap = 0; tap < 9; tap++) {
            const int dr = tap / 3, dc = tap % 3;
            wmma::fragment<wmma::matrix_a, 16, 16, 16, __half, wmma::row_major> af[2];
            #pragma unroll
            for (int cf = 0; cf < 2; cf++)
                wmma::load_matrix_sync(af[cf], s_w + (coSub * 32 + cf * 16) * 144 + tap * 16, 144);
            wmma::fragment<wmma::matrix_b, 16, 16, 16, __half, wmma::col_major> bfr[2];
            #pragma unroll
            for (int nf = 0; nf < 2; nf++) {
                int scol = nSub * 32 + nf * 16 + dc;
                wmma::load_matrix_sync(bfr[nf], s_x + ((rowSub + dr) * 132 + scol) * 16, 16);
            }
            #pragma unroll
            for (int cf = 0; cf < 2; cf++)
                #pragma unroll
                for (int nf = 0; nf < 2; nf++)
                    wmma::mma_sync(acc[cf][nf], af[cf], bfr[nf], acc[cf][nf]);
        }
        __syncthreads();
    }

    #pragma unroll
    for (int r = 0; r < 2; r++) {
        if (rowSub == r) {
            #pragma unroll
            for (int cf = 0; cf < 2; cf++)
                #pragma unroll
                for (int nf = 0; nf < 2; nf++)
                    wmma::store_matrix_sync(
                        sEp + (coSub * 32 + cf * 16) * 136 + (nSub * 32 + nf * 16),
                        acc[cf][nf], 136, wmma::mem_row_major);
        }
        __syncthreads();

        const int h = h0 + r;
        const int px = tid & 127;
        if (ACT == 1) {
            int ch = tid >> 7;
            __half hv[16];
            #pragma unroll
            for (int ci = 0; ci < 16; ci++) {
                int co = ch * 16 + ci;
                float v = sEp[co * 136 + px] + bias[co];
                v = (v >= 0.f) ? v : 0.1f * v;
                hv[ci] = __float2half_rn(v);
            }
            size_t o = (((size_t)(b * 4 + ch) * Hh + h) * Wwidth + px) * 16;
            ((uint4*)(outH + o))[0] = ((const uint4*)hv)[0];
            ((uint4*)(outH + o))[1] = ((const uint4*)hv)[1];
        } else {
            for (int co = tid >> 7; co < 64; co += 4) {
                int oc = coTile * 64 + co;
                if (oc < Co) {
                    float v = sEp[co * 136 + px] + bias[oc];
                    if (ACT == 2) v = 1.f / (1.f + __expf(-v));
                    outF[((size_t)b * Co + oc) * HW + h * Wwidth + px] = v;
                }
            }
        }
        __syncthreads();
    }
}

// Merged om + em1: z=0 -> em1 (longest blocks first), z=1..4 -> om tiles.
__global__ void __launch_bounds__(512) conv_om_em1_kernel(
    const __half* __restrict__ ofi, const __half* __restrict__ si,
    const __half* __restrict__ wom, const __half* __restrict__ we1,
    const float* __restrict__ b_om, const float* __restrict__ b_em1,
    float* __restrict__ omOut, __half* __restrict__ e1Out)
{
    extern __shared__ __align__(16) char smem_raw[];
    if (blockIdx.z == 0)
        conv_body<8, 4, 1>(si, ofi, we1, b_em1, nullptr, e1Out, 64, 0, smem_raw);
    else
        conv_body<4, 4, 0>(ofi, ofi, wom, b_om, omOut, nullptr, 216,
                           blockIdx.z - 1, smem_raw);
}

__global__ void __launch_bounds__(512) conv_em2_kernel(
    const __half* __restrict__ e1i, const __half* __restrict__ we2,
    const float* __restrict__ b_em2, float* __restrict__ emOut)
{
    extern __shared__ __align__(16) char smem_raw[];
    conv_body<4, 4, 2>(e1i, e1i, we2, b_em2, emOut, nullptr, 72,
                       blockIdx.z, smem_raw);
}

// ---------------------------------------------------------------------------
// Both deformable convs. Lane remap: warp = 16 pixels x 2 paths
// (even lane = x half at comb+0, odd lane = share half at comb+8).
// A corner LDG.128 across the warp spans 16 adjacent 32B records = ~5 cache
// lines (vs ~9 for 32-pixel one-path warps) -> ~45% fewer L1 wavefronts.
// Per-output arithmetic order is unchanged (bit-identical results).
// ---------------------------------------------------------------------------
__global__ void __launch_bounds__(256) deform_kernel(
    const float* __restrict__ w_dc, const float* __restrict__ b_dc,
    const __half* __restrict__ comb, float* __restrict__ out)
{
    __shared__ __align__(16) float s_w[8][9][8];
    __shared__ float s_b[8];

    const int tid  = threadIdx.x;
    const int lid  = tid & 31;
    const int warpId = tid >> 5;        // 0..7
    const int p16  = lid >> 1;          // 0..15
    const int half = lid & 1;           // 0 = x, 1 = share
    const int w    = warpId * 16 + p16; // 0..127
    const int h    = blockIdx.x;
    const int bg   = blockIdx.y;
    const int b    = bg >> 3, g = bg & 7;

    for (int e = tid; e < 576; e += 256) {
        int c = e / 72, r = e % 72;
        int kk = r / 8, co = r % 8;
        s_w[c][kk][co] = w_dc[((size_t)(g * 8 + co) * 8 + c) * 9 + kk];
    }
    if (tid < 8) s_b[tid] = b_dc[g * 8 + tid];
    __syncthreads();

    const int pix = h * Wwidth + w;
    const float* omB = g_om + (size_t)b * 216 * HW + pix;
    const float* emB = g_em + (size_t)b * 72 * HW + pix;
    const __half* src = comb + ((size_t)(b * 8 + g) * HW) * 16 + half * 8;

    ull acc[4];
    #pragma unroll
    for (int j = 0; j < 4; j++) acc[j] = 0ull;

    #pragma unroll
    for (int kk = 0; kk < 9; kk++) {
        const int kh = kk / 3, kw = kk % 3;
        float dy = omB[(size_t)(g * 18 + 2 * kk) * HW];
        float dx = omB[(size_t)(g * 18 + 2 * kk + 1) * HW];
        float mask;
        if (half == 0) {
            float mz = omB[(size_t)(144 + g * 9 + kk) * HW];
            mask = 1.f / (1.f + __expf(-mz));
        } else {
            mask = emB[(size_t)(g * 9 + kk) * HW];
        }

        float py = (float)(h - 1 + kh) + dy;
        float px = (float)(w - 1 + kw) + dx;
        float fy = floorf(py), fx = floorf(px);
        float ly = py - fy, lx = px - fx;
        int y0 = (int)fy, x0 = (int)fx;
        int y1 = y0 + 1, x1 = x0 + 1;

        float w00 = (1.f - ly) * (1.f - lx);
        float w01 = (1.f - ly) * lx;
        float w10 = ly * (1.f - lx);
        float w11 = ly * lx;
        if (y0 < 0 || y0 >= Hh)     { w00 = 0.f; w01 = 0.f; }
        if (y1 < 0 || y1 >= Hh)     { w10 = 0.f; w11 = 0.f; }
        if (x0 < 0 || x0 >= Wwidth) { w00 = 0.f; w10 = 0.f; }
        if (x1 < 0 || x1 >= Wwidth) { w01 = 0.f; w11 = 0.f; }

        int cy0 = min(max(y0, 0), Hh - 1),     cy1 = min(max(y1, 0), Hh - 1);
        int cx0 = min(max(x0, 0), Wwidth - 1), cx1 = min(max(x1, 0), Wwidth - 1);
        int i00 = (cy0 * Wwidth + cx0) * 16, i01 = (cy0 * Wwidth + cx1) * 16;
        int i10 = (cy1 * Wwidth + cx0) * 16, i11 = (cy1 * Wwidth + cx1) * 16;

        float4 r00 = *(const float4*)(src + i00);
        float4 r01 = *(const float4*)(src + i01);
        float4 r10 = *(const float4*)(src + i10);
        float4 r11 = *(const float4*)(src + i11);
        const __half2* h00 = (const __half2*)&r00;
        const __half2* h01 = (const __half2*)&r01;
        const __half2* h10 = (const __half2*)&r10;
        const __half2* h11 = (const __half2*)&r11;

        float vv[8];
        #pragma unroll
        for (int j2 = 0; j2 < 4; j2++) {
            float2 f00 = __half22float2(h00[j2]);
            float2 f01 = __half22float2(h01[j2]);
            float2 f10 = __half22float2(h10[j2]);
            float2 f11 = __half22float2(h11[j2]);
            vv[2 * j2]     = (w00 * f00.x + w01 * f01.x + w10 * f10.x + w11 * f11.x) * mask;
            vv[2 * j2 + 1] = (w00 * f00.y + w01 * f01.y + w10 * f10.y + w11 * f11.y) * mask;
        }

        #pragma unroll
        for (int c = 0; c < 8; c++) {
            ull xs = pk(vv[c], vv[c]);
            #pragma unroll
            for (int j = 0; j < 4; j++) {
                ull wp = *(const ull*)&s_w[c][kk][2 * j];
                acc[j] = ffma2(xs, wp, acc[j]);
            }
        }
    }

    float* ob = out + (size_t)half * Bn * 64 * HW + (size_t)(b * 64 + g * 8) * HW + pix;
    #pragma unroll
    for (int j = 0; j < 4; j++) {
        float v0, v1;
        upk(acc[j], v0, v1);
        ob[(size_t)(2 * j) * HW]     = v0 + s_b[2 * j];
        ob[(size_t)(2 * j + 1) * HW] = v1 + s_b[2 * j + 1];
    }
}

// ---------------------------------------------------------------------------
extern "C" void kernel_launch(void* const* d_in, const int* in_sizes, int n_in,
                              void* d_out, int out_size)
{
    const float* x      = (const float*)d_in[0];
    const float* share  = (const float*)d_in[1];
    const float* offF   = (const float*)d_in[2];
    const float* w_om   = (const float*)d_in[3];
    const float* b_om   = (const float*)d_in[4];
    const float* w_em1  = (const float*)d_in[5];
    const float* b_em1  = (const float*)d_in[6];
    const float* w_em2  = (const float*)d_in[7];
    const float* b_em2  = (const float*)d_in[8];
    const float* w_dc   = (const float*)d_in[9];
    const float* b_dc   = (const float*)d_in[10];
    float* out = (float*)d_out;

    float *pom, *pem;
    __half *psi, *pofi, *pe1i, *pcomb, *pwom, *pwe1, *pwe2;
    cudaGetSymbolAddress((void**)&pom,   g_om);
    cudaGetSymbolAddress((void**)&pem,   g_em);
    cudaGetSymbolAddress((void**)&psi,   g_si);
    cudaGetSymbolAddress((void**)&pofi,  g_ofi);
    cudaGetSymbolAddress((void**)&pe1i,  g_e1i);
    cudaGetSymbolAddress((void**)&pcomb, g_comb);
    cudaGetSymbolAddress((void**)&pwom,  g_wom);
    cudaGetSymbolAddress((void**)&pwe1,  g_we1);
    cudaGetSymbolAddress((void**)&pwe2,  g_we2);

    cudaFuncSetAttribute(conv_om_em1_kernel,
                         cudaFuncAttributeMaxDynamicSharedMemorySize, SMEM_CONV);
    cudaFuncSetAttribute(conv_em2_kernel,
                         cudaFuncAttributeMaxDynamicSharedMemorySize, SMEM_CONV);

    // 4 launches; ncu profiles launch #4 -> deform_kernel
    prep_kernel<<<SPLIT_BLOCKS + PACK_BLOCKS, 256>>>(                             // 1
        x, share, offF, w_om, w_em1, w_em2,
        pofi, psi, pcomb, pwom, pwe1, pwe2);
    conv_om_em1_kernel<<<dim3(64, 4, 5), 512, SMEM_CONV>>>(                       // 2
        pofi, psi, pwom, pwe1, b_om, b_em1, pom, pe1i);
    conv_em2_kernel<<<dim3(64, 4, 2), 512, SMEM_CONV>>>(                          // 3
        pe1i, pwe2, b_em2, pem);
    deform_kernel<<<dim3(128, 32), 256>>>(w_dc, b_dc, pcomb, out);                // 4

    (void)in_sizes; (void)n_in; (void)out_size;
}